// round 9
// baseline (speedup 1.0000x reference)
#include <cuda_runtime.h>
#include <cuda_bf16.h>
#include <math.h>
#include <string.h>

#define BN 32
#define TIN 256
#define TOUT 400
#define EDIM 512
#define ADIM 128
#define NFLT 32
#define KSZ 31
#define PRE 256
#define DDIM 1024
#define NMEL 80
#define ZN 4096
#define NCTA 128
#define NTHR 512
#define CHUNKK 256
#define KST0 112
#define KST1 160

// dynamic smem layout
#define OFF_BB 0              // 3 * 32768 B buffers
#define OFF_XH 98304          // 2 * 16384 A-hi (fragment order)
#define OFF_XL 131072         // 2 * 16384 A-lo
#define OFF_ZF 163840         // 4096
#define DSMEM_BYTES 167936

// ---------------- persistent device scratch ----------------
__device__ float g_prenet[TOUT * BN * PRE];
__device__ float g_keysT[BN * ADIM * TIN];
__device__ float g_maskneg[BN * TIN];
__device__ float g_h0[2][BN * DDIM];
__device__ float g_h1[2][BN * DDIM];
__device__ float g_ctx[BN * EDIM];
__device__ float g_wcum[BN * TIN];
__device__ float g_epart[4 * BN * TIN];
__device__ float g_h1all[TOUT * BN * DDIM];
__device__ float g_ctxall[TOUT * BN * EDIM];
__device__ unsigned g_barc;
__device__ volatile unsigned g_barg;
__device__ uint4 g_pb0[(size_t)NCTA * KST0 * 4 * 32];
__device__ uint4 g_pb1[(size_t)NCTA * KST1 * 4 * 32];

__device__ __forceinline__ float sigmoidf_(float x) { return 1.f / (1.f + expf(-x)); }

__device__ __forceinline__ unsigned smem_u32(const void* p) {
    unsigned a;
    asm("{ .reg .u64 t; cvta.to.shared.u64 t, %1; cvt.u32.u64 %0, t; }"
        : "=r"(a) : "l"(p));
    return a;
}
__device__ __forceinline__ void cpasync16(unsigned dst, const void* src) {
    asm volatile("cp.async.cg.shared.global [%0], [%1], 16;" :: "r"(dst), "l"(src));
}
#define CP_COMMIT() asm volatile("cp.async.commit_group;" ::: "memory")
#define CP_WAITG(n) asm volatile("cp.async.wait_group %0;" :: "n"(n) : "memory")

__device__ __forceinline__ unsigned pk2(__nv_bfloat16 a, __nv_bfloat16 b) {
    __nv_bfloat162 t(a, b);
    unsigned r;
    memcpy(&r, &t, 4);
    return r;
}
__device__ __forceinline__ void mma16816(float& d0, float& d1, float& d2, float& d3,
                                         unsigned a0, unsigned a1, unsigned a2,
                                         unsigned a3, unsigned b0, unsigned b1) {
    asm volatile("mma.sync.aligned.m16n8k16.row.col.f32.bf16.bf16.f32 "
                 "{%0,%1,%2,%3}, {%4,%5,%6,%7}, {%8,%9}, {%0,%1,%2,%3};"
                 : "+f"(d0), "+f"(d1), "+f"(d2), "+f"(d3)
                 : "r"(a0), "r"(a1), "r"(a2), "r"(a3), "r"(b0), "r"(b1));
}

// ---------------- grid barrier ----------------
__device__ __forceinline__ void grid_bar() {
    __syncthreads();
    if (threadIdx.x == 0) {
        __threadfence();
        unsigned gen = g_barg;
        if (atomicInc(&g_barc, NCTA - 1) == NCTA - 1) {
            g_barg = gen + 1;
            __threadfence();
        } else {
            while (g_barg == gen) __nanosleep(32);
        }
        __threadfence();
    }
    __syncthreads();
}

// ---------------- attention smem structs (alias GEMM region) ------------
struct AttC {
    float wp[TIN + KSZ];
    float cws[KSZ * NFLT];
    float cbs[NFLT];
    float ldws[NFLT * 32];
    float ldbs[32], vws[32];
    float qred[16][32];
    float qp[32];
    float es[2][TIN];
    float loc[TIN][NFLT + 1];
};
struct AttD { float red[256]; float ws[256]; float cred[4][128]; };

// ---------------- combined weight pack (both matrices, one launch) -------
__device__ void pack_tile(const float* __restrict__ wK, const float* __restrict__ wR,
                          int KST, int KB1, uint4* __restrict__ out,
                          int ks, int nb, float (*w)[128]) {
    int k0 = ks * 16;
    const float* W = (k0 < KB1) ? wK + (size_t)k0 * ZN : wR + (size_t)(k0 - KB1) * ZN;
    int N0 = nb * 128;
    for (int i = threadIdx.x; i < 2048; i += 256)
        w[i >> 7][i & 127] = W[(size_t)(i >> 7) * ZN + N0 + (i & 127)];
    __syncthreads();
    int g = N0 >> 10, jbase = (N0 & 1023) >> 3;
    for (int s = threadIdx.x; s < 512; s += 256) {
        int jl = s >> 5, lane = s & 31;
        int q = lane & 3, t4 = lane >> 2;
        int n = jl * 8 + t4;
        float v0 = w[2 * q][n], v1 = w[2 * q + 1][n];
        float v2 = w[2 * q + 8][n], v3 = w[2 * q + 9][n];
        __nv_bfloat16 h0 = __float2bfloat16_rn(v0), h1 = __float2bfloat16_rn(v1);
        __nv_bfloat16 h2 = __float2bfloat16_rn(v2), h3 = __float2bfloat16_rn(v3);
        unsigned bh0 = pk2(h0, h1), bh1 = pk2(h2, h3);
        unsigned bl0 = pk2(__float2bfloat16_rn(v0 - __bfloat162float(h0)),
                           __float2bfloat16_rn(v1 - __bfloat162float(h1)));
        unsigned bl1 = pk2(__float2bfloat16_rn(v2 - __bfloat162float(h2)),
                           __float2bfloat16_rn(v3 - __bfloat162float(h3)));
        int jj = jbase + jl;
        out[((size_t)(jj * KST + ks) * 4 + g) * 32 + lane] = make_uint4(bh0, bh1, bl0, bl1);
    }
}

__global__ void pack_all_kernel(const float* __restrict__ l0k, const float* __restrict__ l0r,
                                const float* __restrict__ l1k, const float* __restrict__ l1r,
                                uint4* __restrict__ o0, uint4* __restrict__ o1) {
    __shared__ float w[16][128];
    int bid = blockIdx.x;
    if (bid < KST0 * 32)
        pack_tile(l0k, l0r, KST0, 768, o0, bid % KST0, bid / KST0, w);
    else {
        bid -= KST0 * 32;
        pack_tile(l1k, l1r, KST1, 1536, o1, bid % KST1, bid / KST1, w);
    }
}

// ---------------- bf16 MMA GEMM, CHUNKK=256, fragment-order A staging ------
// warps 0..7 consumers; 8..15 producers. zf[row*32 + 8g + i] result.
template <int KTOT, int KB0, int KB1, int SA>
__device__ __forceinline__ void gemm_mma(char* dsm, int j,
                                         const float* __restrict__ xA,
                                         const float* __restrict__ xB,
                                         const float* __restrict__ xC,
                                         const uint4* __restrict__ pB,
                                         float* __restrict__ zf) {
    constexpr int NC = KTOT / CHUNKK;
    constexpr int KST = KTOT / 16;
    const int tid = threadIdx.x;
    uint4* Bb = (uint4*)(dsm + OFF_BB);            // [3][2048]
    unsigned* xhU = (unsigned*)(dsm + OFF_XH);     // [2][2][16][32][4]
    unsigned* xlU = (unsigned*)(dsm + OFF_XL);

    if (tid >= 256) {
        // ---- producers ----
        const int p = tid - 256;
        const int row = p >> 3, kseg = p & 7;
        const int mi = row >> 4, rloc = row & 15, t4 = rloc & 7, rbit = rloc >> 3;
        float4 xr[8];
        auto ldgx = [&](int c) {
            int k0 = c * CHUNKK + kseg * 32;
            const float* s;
            if (k0 < KB0)      s = xA + row * SA + k0;
            else if (k0 < KB1) s = xB + row * EDIM + (k0 - KB0);
            else               s = xC + row * DDIM + (k0 - KB1);
            #pragma unroll
            for (int i = 0; i < 8; i++) xr[i] = __ldcg((const float4*)s + i);
        };
        auto stsx = [&](int c) {
            int boff = (c & 1) * 4096;             // uint units per buffer set
            float f[32];
            #pragma unroll
            for (int i = 0; i < 8; i++) {
                f[4 * i] = xr[i].x;     f[4 * i + 1] = xr[i].y;
                f[4 * i + 2] = xr[i].z; f[4 * i + 3] = xr[i].w;
            }
            #pragma unroll
            for (int u = 0; u < 16; u++) {
                int k2 = kseg * 16 + u;            // k-pair within chunk
                int ksg = k2 >> 3, p8 = k2 & 7;
                int q = p8 & 3, kh = p8 >> 2;
                int idx = boff + (((mi * 16 + ksg) * 32) + t4 * 4 + q) * 4 +
                          (rbit | (kh << 1));
                float a = f[2 * u], b = f[2 * u + 1];
                __nv_bfloat16 ha = __float2bfloat16_rn(a), hb = __float2bfloat16_rn(b);
                xhU[idx] = pk2(ha, hb);
                xlU[idx] = pk2(__float2bfloat16_rn(a - __bfloat162float(ha)),
                               __float2bfloat16_rn(b - __bfloat162float(hb)));
            }
        };
        auto cpB = [&](int c) {
            const char* src = (const char*)(pB + (size_t)(j * KST + c * 16) * 128);
            char* dst = (char*)(Bb + (size_t)(c % 3) * 2048);
            #pragma unroll
            for (int i = 0; i < 8; i++) {
                int e = (p + 256 * i) * 16;
                cpasync16(smem_u32(dst + e), src + e);
            }
            CP_COMMIT();
        };

        ldgx(0);
        cpB(0); cpB(1);
        stsx(0);
        ldgx(1);
        CP_WAITG(1);
        __syncthreads();
        for (int c = 0; c < NC; c++) {
            if (c + 1 < NC) {
                stsx(c + 1);
                if (c + 2 < NC) ldgx(c + 2);
            }
            if (c + 2 < NC) { cpB(c + 2); CP_WAITG(1); }
            else if (c + 1 < NC) CP_WAITG(0);
            __syncthreads();
        }
    } else {
        // ---- consumers ----
        const int w = tid >> 5, lane = tid & 31;
        const int mi = w & 1, g = w >> 1;
        const int t4 = lane >> 2, q = lane & 3;
        const int r0 = mi * 16 + t4;
        const uint4* xh4 = (const uint4*)(dsm + OFF_XH);
        const uint4* xl4 = (const uint4*)(dsm + OFF_XL);
        float d0 = 0.f, d1 = 0.f, d2 = 0.f, d3 = 0.f;
        __syncthreads();
        for (int c = 0; c < NC; c++) {
            const uint4* Bw = Bb + (c % 3) * 2048 + g * 32 + lane;
            const uint4* xhb = xh4 + (c & 1) * 1024 + mi * 512 + lane;
            const uint4* xlb = xl4 + (c & 1) * 1024 + mi * 512 + lane;
            #pragma unroll
            for (int ksg = 0; ksg < 16; ksg++) {
                uint4 A = xhb[ksg * 32];
                uint4 L = xlb[ksg * 32];
                uint4 B = Bw[ksg * 128];
                mma16816(d0, d1, d2, d3, A.x, A.y, A.z, A.w, B.x, B.y);
                mma16816(d0, d1, d2, d3, L.x, L.y, L.z, L.w, B.x, B.y);
                mma16816(d0, d1, d2, d3, A.x, A.y, A.z, A.w, B.z, B.w);
            }
            __syncthreads();
        }
        zf[r0 * 32 + g * 8 + 2 * q]           = d0;
        zf[r0 * 32 + g * 8 + 2 * q + 1]       = d1;
        zf[(r0 + 8) * 32 + g * 8 + 2 * q]     = d2;
        zf[(r0 + 8) * 32 + g * 8 + 2 * q + 1] = d3;
    }
    __syncthreads();
}

// ---------------- persistent decoder kernel ----------------
__global__ __launch_bounds__(NTHR, 1) void decoder_persist(
    const float* __restrict__ memory,
    const float* __restrict__ l0b, const float* __restrict__ l1b,
    const float* __restrict__ qw, const float* __restrict__ qb,
    const float* __restrict__ vw, const float* __restrict__ vb,
    const float* __restrict__ cw, const float* __restrict__ cb,
    const float* __restrict__ ldw, const float* __restrict__ ldb,
    float* __restrict__ out_align) {
    extern __shared__ char dsm[];
    float* zf = (float*)(dsm + OFF_ZF);
    AttC* sc = (AttC*)dsm;
    AttD* sd = (AttD*)dsm;
    const int j = blockIdx.x;
    const int tid = threadIdx.x;

    {   // init state
        int i = j * NTHR + tid;
        if (i < BN * DDIM) {
            g_h0[0][i] = 0.f; g_h0[1][i] = 0.f;
            g_h1[0][i] = 0.f; g_h1[1][i] = 0.f;
        }
        if (i < BN * EDIM) g_ctx[i] = 0.f;
        if (i < BN * TIN)  g_wcum[i] = 0.f;
    }
    float c0r = 0.f, c1r = 0.f;
    const int bq = tid >> 3, dd = tid & 7;
    const int du = 8 * j + dd;
    const int ab = j >> 2, ach = j & 3;

    grid_bar();

    for (int t = 0; t < TOUT; t++) {
        const int rb = t & 1, wb = (t + 1) & 1;

        // ---- phase A: LSTM0 GEMM + gates ----
        gemm_mma<1792, 256, 768, PRE>(dsm, j, g_prenet + (size_t)t * BN * PRE,
                                      g_ctx, g_h0[rb], g_pb0, zf);
        if (tid < 256) {
            float zi  = zf[bq * 32 + dd]      + l0b[du];
            float zff = zf[bq * 32 + 8 + dd]  + l0b[1024 + du];
            float zg  = zf[bq * 32 + 16 + dd] + l0b[2048 + du];
            float zo  = zf[bq * 32 + 24 + dd] + l0b[3072 + du];
            float ii = sigmoidf_(zi), ff = sigmoidf_(zff), oo = sigmoidf_(zo);
            c0r = ff * c0r + ii * tanhf(zg);
            __stcg(&g_h0[wb][bq * DDIM + du], oo * tanhf(c0r));
        }
        grid_bar();

        // ---- phase B: LSTM1 GEMM + gates ----
        gemm_mma<2560, 1024, 1536, DDIM>(dsm, j, g_h0[wb], g_ctx, g_h1[rb],
                                         g_pb1, zf);
        if (tid < 256) {
            float zi  = zf[bq * 32 + dd]      + l1b[du];
            float zff = zf[bq * 32 + 8 + dd]  + l1b[1024 + du];
            float zg  = zf[bq * 32 + 16 + dd] + l1b[2048 + du];
            float zo  = zf[bq * 32 + 24 + dd] + l1b[3072 + du];
            float ii = sigmoidf_(zi), ff = sigmoidf_(zff), oo = sigmoidf_(zo);
            c1r = ff * c1r + ii * tanhf(zg);
            float h = oo * tanhf(c1r);
            __stcg(&g_h1[wb][bq * DDIM + du], h);
            g_h1all[((size_t)t * BN + bq) * DDIM + du] = h;
        }
        grid_bar();

        // ---- phase C: attention energies (CTA = b x a-chunk) ----
        {
            const float* h1cur = g_h1[wb];
            {
                int al = tid & 31, part = tid >> 5;
                float a0 = 0.f;
                int k0 = part * 64;
                #pragma unroll 4
                for (int k = k0; k < k0 + 64; k++)
                    a0 += __ldcg(h1cur + ab * DDIM + k) * qw[k * ADIM + ach * 32 + al];
                sc->qred[part][al] = a0;
            }
            for (int i = tid; i < TIN + KSZ - 1; i += NTHR) {
                int jj = i - (KSZ / 2);
                sc->wp[i] = (jj >= 0 && jj < TIN) ? __ldcg(&g_wcum[ab * TIN + jj]) : 0.f;
            }
            for (int i = tid; i < KSZ * NFLT; i += NTHR) sc->cws[i] = cw[i];
            if (tid < NFLT) sc->cbs[tid] = cb[tid];
            for (int i = tid; i < NFLT * 32; i += NTHR)
                sc->ldws[i] = ldw[(i >> 5) * ADIM + ach * 32 + (i & 31)];
            if (tid < 32) {
                sc->ldbs[tid] = ldb[ach * 32 + tid];
                sc->vws[tid]  = vw[ach * 32 + tid];
            }
            __syncthreads();
            if (tid < 32) {
                float s = 0.f;
                #pragma unroll
                for (int p = 0; p < 16; p++) s += sc->qred[p][tid];
                sc->qp[tid] = s + qb[ach * 32 + tid];
            }
            {
                int ti = tid & 255, fh = tid >> 8;
                float lf[16];
                #pragma unroll
                for (int f = 0; f < 16; f++) lf[f] = sc->cbs[fh * 16 + f];
                for (int jk = 0; jk < KSZ; jk++) {
                    float w = sc->wp[ti + jk];
                    #pragma unroll
                    for (int f = 0; f < 16; f++)
                        lf[f] += w * sc->cws[jk * NFLT + fh * 16 + f];
                }
                #pragma unroll
                for (int f = 0; f < 16; f++) sc->loc[ti][fh * 16 + f] = lf[f];
            }
            __syncthreads();
            {
                int ti = tid & 255, ah = tid >> 8;
                float locv[NFLT];
                #pragma unroll
                for (int f = 0; f < NFLT; f++) locv[f] = sc->loc[ti][f];
                float e = 0.f;
                #pragma unroll 4
                for (int al16 = 0; al16 < 16; al16++) {
                    int al = ah * 16 + al16;
                    int a = ach * 32 + al;
                    float s = sc->qp[al] + g_keysT[(ab * ADIM + a) * TIN + ti] +
                              sc->ldbs[al];
                    #pragma unroll
                    for (int f = 0; f < NFLT; f++) s += locv[f] * sc->ldws[f * 32 + al];
                    e += tanhf(s) * sc->vws[al];
                }
                sc->es[ah][ti] = e;
            }
            __syncthreads();
            if (tid < 256)
                __stcg(&g_epart[(ach * BN + ab) * TIN + tid],
                       sc->es[0][tid] + sc->es[1][tid]);
        }
        grid_bar();

        // ---- phase D: softmax + context (CTA = b x E-chunk) ----
        {
            const int ec = ach;
            float ev = 0.f, ex = 0.f;
            if (tid < 256) {
                ev = vb[0] + g_maskneg[ab * TIN + tid];
                #pragma unroll
                for (int ac = 0; ac < 4; ac++)
                    ev += __ldcg(&g_epart[(ac * BN + ab) * TIN + tid]);
                sd->red[tid] = ev;
            }
            __syncthreads();
            for (int s = 128; s > 0; s >>= 1) {
                if (tid < s) sd->red[tid] = fmaxf(sd->red[tid], sd->red[tid + s]);
                __syncthreads();
            }
            float mx = sd->red[0];
            __syncthreads();
            if (tid < 256) { ex = expf(ev - mx); sd->red[tid] = ex; }
            __syncthreads();
            for (int s = 128; s > 0; s >>= 1) {
                if (tid < s) sd->red[tid] += sd->red[tid + s];
                __syncthreads();
            }
            float inv = 1.f / sd->red[0];
            __syncthreads();
            if (tid < 256) {
                float w = ex * inv;
                sd->ws[tid] = w;
                if (ec == 0) {
                    __stcg(&g_wcum[ab * TIN + tid],
                           __ldcg(&g_wcum[ab * TIN + tid]) + w);
                    out_align[((size_t)ab * TOUT + t) * TIN + tid] = w;
                }
            }
            __syncthreads();
            {
                int cl = tid & 127, q = tid >> 7;
                float acc = 0.f;
                #pragma unroll 4
                for (int tt = q * 64; tt < q * 64 + 64; tt++)
                    acc += sd->ws[tt] *
                           memory[((size_t)ab * TIN + tt) * EDIM + ec * 128 + cl];
                sd->cred[q][cl] = acc;
                __syncthreads();
                if (tid < 128) {
                    float cv = sd->cred[0][tid] + sd->cred[1][tid] +
                               sd->cred[2][tid] + sd->cred[3][tid];
                    __stcg(&g_ctx[ab * EDIM + ec * 128 + tid], cv);
                    g_ctxall[((size_t)t * BN + ab) * EDIM + ec * 128 + tid] = cv;
                }
            }
        }
        grid_bar();
    }
}

// ---------------- prenet (+ mask build in block 0) ----------------
__global__ void prenet_kernel(const float* __restrict__ targets,
                              const float* __restrict__ w1, const float* __restrict__ b1,
                              const float* __restrict__ w2, const float* __restrict__ b2,
                              const unsigned char* __restrict__ mask) {
    int bid = blockIdx.x;
    int t = bid >> 5, b = bid & 31;
    __shared__ float xin[NMEL];
    __shared__ float h[PRE];
    __shared__ int s_has;
    int tid = threadIdx.x;
    if (tid < NMEL) xin[tid] = (t == 0) ? 0.f : targets[(b * TOUT + (t - 1)) * NMEL + tid];
    __syncthreads();
    float acc = b1[tid];
    #pragma unroll 8
    for (int k = 0; k < NMEL; k++) acc += xin[k] * w1[k * PRE + tid];
    h[tid] = fmaxf(acc, 0.f);
    __syncthreads();
    float acc2 = b2[tid];
    #pragma unroll 8
    for (int k = 0; k < PRE; k++) acc2 += h[k] * w2[k * PRE + tid];
    g_prenet[(t * BN + b) * PRE + tid] = fmaxf(acc2, 0.f);

    if (bid == 0) {   // mask dtype detect + maskneg
        if (tid == 0) s_has = 0;
        __syncthreads();
        int local = 0;
        for (int i = tid; i < BN * TIN; i += 256)
            if ((i & 3) != 0 && mask[i] != 0) local = 1;
        if (local) atomicOr(&s_has, 1);
        __syncthreads();
        bool is_u8 = (s_has != 0);
        const int* mi = (const int*)mask;
        for (int i = tid; i < BN * TIN; i += 256) {
            int v = is_u8 ? (int)mask[i] : mi[i];
            g_maskneg[i] = v ? 0.f : -1e9f;
        }
    }
}

// ---------------- keys projection ----------------
__global__ void keys_kernel(const float* __restrict__ memory,
                            const float* __restrict__ mw, const float* __restrict__ mb) {
    int bid = blockIdx.x;
    int b = bid >> 8, t = bid & 255;
    __shared__ float x[EDIM];
    int tid = threadIdx.x;
    for (int i = tid; i < EDIM; i += 128) x[i] = memory[(b * TIN + t) * EDIM + i];
    __syncthreads();
    float acc = mb[tid];
    #pragma unroll 8
    for (int k = 0; k < EDIM; k++) acc += x[k] * mw[k * ADIM + tid];
    g_keysT[(b * ADIM + tid) * TIN + t] = acc;
}

// ---------------- output projections ----------------
__global__ void proj_kernel(const float* __restrict__ pw, const float* __restrict__ pb,
                            const float* __restrict__ gw, const float* __restrict__ gb,
                            float* __restrict__ out_mel, float* __restrict__ out_gate) {
    int bid = blockIdx.x;
    int t = bid >> 5, b = bid & 31;
    __shared__ float xo[DDIM + EDIM];
    int tid = threadIdx.x;
    for (int i = tid; i < DDIM; i += 128) xo[i] = g_h1all[(size_t)(t * BN + b) * DDIM + i];
    for (int i = tid; i < EDIM; i += 128) xo[DDIM + i] = g_ctxall[(size_t)(t * BN + b) * EDIM + i];
    __syncthreads();
    if (tid < NMEL) {
        float acc = pb[tid];
        #pragma unroll 8
        for (int k = 0; k < DDIM + EDIM; k++) acc += xo[k] * pw[k * NMEL + tid];
        out_mel[(size_t)(b * TOUT + t) * NMEL + tid] = acc;
    } else if (tid == NMEL) {
        float acc = gb[0];
        for (int k = 0; k < DDIM + EDIM; k++) acc += xo[k] * gw[k];
        out_gate[b * TOUT + t] = acc;
    }
}

// ---------------- launcher ----------------
extern "C" void kernel_launch(void* const* d_in, const int* in_sizes, int n_in,
                              void* d_out, int out_size) {
    (void)in_sizes; (void)n_in; (void)out_size;
    const float* memory  = (const float*)d_in[0];
    const float* targets = (const float*)d_in[1];
    const unsigned char* mask = (const unsigned char*)d_in[2];
    const float* p1w = (const float*)d_in[3];
    const float* p1b = (const float*)d_in[4];
    const float* p2w = (const float*)d_in[5];
    const float* p2b = (const float*)d_in[6];
    const float* l0k = (const float*)d_in[7];
    const float* l0r = (const float*)d_in[8];
    const float* l0b = (const float*)d_in[9];
    const float* l1k = (const float*)d_in[10];
    const float* l1r = (const float*)d_in[11];
    const float* l1b = (const float*)d_in[12];
    const float* qw  = (const float*)d_in[13];
    const float* qb  = (const float*)d_in[14];
    const float* mw  = (const float*)d_in[15];
    const float* mb  = (const float*)d_in[16];
    const float* vw  = (const float*)d_in[17];
    const float* vb  = (const float*)d_in[18];
    const float* ccw = (const float*)d_in[19];
    const float* ccb = (const float*)d_in[20];
    const float* ldw = (const float*)d_in[21];
    const float* ldb = (const float*)d_in[22];
    const float* pw  = (const float*)d_in[23];
    const float* pb  = (const float*)d_in[24];
    const float* gw  = (const float*)d_in[25];
    const float* gb  = (const float*)d_in[26];

    float* out       = (float*)d_out;
    float* out_mel   = out;
    float* out_gate  = out + (size_t)BN * TOUT * NMEL;
    float* out_align = out_gate + (size_t)BN * TOUT;

    static int smem_set = 0;
    if (!smem_set) {
        cudaFuncSetAttribute(decoder_persist,
                             cudaFuncAttributeMaxDynamicSharedMemorySize, DSMEM_BYTES);
        smem_set = 1;
    }

    uint4* pb0;
    uint4* pb1;
    cudaGetSymbolAddress((void**)&pb0, g_pb0);
    cudaGetSymbolAddress((void**)&pb1, g_pb1);

    pack_all_kernel<<<(KST0 + KST1) * 32, 256>>>(l0k, l0r, l1k, l1r, pb0, pb1);
    prenet_kernel<<<TOUT * BN, 256>>>(targets, p1w, p1b, p2w, p2b, mask);
    keys_kernel<<<BN * TIN, 128>>>(memory, mw, mb);
    decoder_persist<<<NCTA, NTHR, DSMEM_BYTES>>>(memory, l0b, l1b, qw, qb, vw, vb,
                                                 ccw, ccb, ldw, ldb, out_align);
    proj_kernel<<<TOUT * BN, 128>>>(pw, pb, gw, gb, out_mel, out_gate);
}